// round 2
// baseline (speedup 1.0000x reference)
#include <cuda_runtime.h>
#include <cuda_bf16.h>
#include <cstddef>

// ---------------------------------------------------------------------------
// BiGRU: B=32, S=512, I=512, H=512, L=2, bidirectional.
//   gx  = x @ wx^T + bx  (precomputed GEMM, [dir][s][b][3H])
//   per step: gh = h @ wh^T + bh
//     r = sig(gx_r+gh_r); z = sig(gx_z+gh_z); n = tanh(gx_n + r*gh_n)
//     h = (1-z)*n + z*h
// Recurrence: ONE persistent kernel per layer (both dirs), software grid
// barrier per direction between steps. 5 graph nodes total.
// ---------------------------------------------------------------------------

#define BATCH 32
#define SEQ   512
#define HID   512
#define G3H   1536
#define MROWS (SEQ * BATCH)   // 16384

// scratch (allocation-free rule: __device__ globals)
__device__ float g_gx[(size_t)2 * MROWS * G3H];          // ~201 MB, reused per layer
__device__ float g_y0[(size_t)BATCH * SEQ * 2 * HID];    // ~67 MB layer-0 output
__device__ unsigned g_arrive[2];                          // per-direction barrier
__device__ unsigned g_gen[2];                             // monotonic generation

// ---------------------------------------------------------------------------
// acquire/release helpers for the inter-block barrier
// ---------------------------------------------------------------------------
__device__ __forceinline__ unsigned atom_add_release(unsigned* p, unsigned v) {
    unsigned old;
    asm volatile("atom.add.release.gpu.u32 %0, [%1], %2;"
                 : "=r"(old) : "l"(p), "r"(v) : "memory");
    return old;
}
__device__ __forceinline__ unsigned ld_acquire(unsigned* p) {
    unsigned v;
    asm volatile("ld.acquire.gpu.u32 %0, [%1];" : "=r"(v) : "l"(p) : "memory");
    return v;
}

// ---------------------------------------------------------------------------
// GEMM: gx[dir][s][b][n] = sum_k X[b][s][k] * W_dir[n][k] + bias_dir[n]
// X layout [B][S][in_dim]. M index m = s*32 + b. 128x128x16 tile, 8x8/thread.
// ---------------------------------------------------------------------------
#define BM 128
#define BN 128
#define BK 16

__global__ void __launch_bounds__(256) gemm_gx(
    const float* __restrict__ X, int in_dim,
    const float* __restrict__ Wf, const float* __restrict__ bf,
    const float* __restrict__ Wb, const float* __restrict__ bb)
{
    __shared__ float As[BK][BM];
    __shared__ float Bs[BK][BN];

    const int dir = blockIdx.z;
    const float* W    = dir ? Wb : Wf;
    const float* bias = dir ? bb : bf;
    const int m0 = blockIdx.x * BM;
    const int n0 = blockIdx.y * BN;
    const int tid = threadIdx.x;
    const int tx = tid & 15;      // n micro-tile
    const int ty = tid >> 4;      // m micro-tile

    float acc[8][8];
#pragma unroll
    for (int i = 0; i < 8; i++)
#pragma unroll
        for (int j = 0; j < 8; j++) acc[i][j] = 0.f;

    for (int k0 = 0; k0 < in_dim; k0 += BK) {
#pragma unroll
        for (int ld = 0; ld < 2; ld++) {
            int idx = tid + ld * 256;          // 0..511
            int row = idx >> 2;                // 0..127
            int kq  = (idx & 3) << 2;          // 0,4,8,12
            int m = m0 + row;
            const float4 av = *(const float4*)(X +
                ((size_t)(m & 31) * SEQ + (size_t)(m >> 5)) * in_dim + k0 + kq);
            As[kq + 0][row] = av.x; As[kq + 1][row] = av.y;
            As[kq + 2][row] = av.z; As[kq + 3][row] = av.w;
            const float4 bv = *(const float4*)(W +
                (size_t)(n0 + row) * in_dim + k0 + kq);
            Bs[kq + 0][row] = bv.x; Bs[kq + 1][row] = bv.y;
            Bs[kq + 2][row] = bv.z; Bs[kq + 3][row] = bv.w;
        }
        __syncthreads();

#pragma unroll
        for (int k = 0; k < BK; k++) {
            float4 a0 = *(const float4*)&As[k][ty * 8];
            float4 a1 = *(const float4*)&As[k][ty * 8 + 4];
            float4 b0 = *(const float4*)&Bs[k][tx * 8];
            float4 b1 = *(const float4*)&Bs[k][tx * 8 + 4];
            float a[8] = {a0.x, a0.y, a0.z, a0.w, a1.x, a1.y, a1.z, a1.w};
            float b[8] = {b0.x, b0.y, b0.z, b0.w, b1.x, b1.y, b1.z, b1.w};
#pragma unroll
            for (int i = 0; i < 8; i++)
#pragma unroll
                for (int j = 0; j < 8; j++)
                    acc[i][j] = fmaf(a[i], b[j], acc[i][j]);
        }
        __syncthreads();
    }

    float4 bia0 = *(const float4*)(bias + n0 + tx * 8);
    float4 bia1 = *(const float4*)(bias + n0 + tx * 8 + 4);
#pragma unroll
    for (int i = 0; i < 8; i++) {
        int m = m0 + ty * 8 + i;
        float* outp = g_gx + ((size_t)dir * MROWS + m) * G3H + n0 + tx * 8;
        float4 v0, v1;
        v0.x = acc[i][0] + bia0.x; v0.y = acc[i][1] + bia0.y;
        v0.z = acc[i][2] + bia0.z; v0.w = acc[i][3] + bia0.w;
        v1.x = acc[i][4] + bia1.x; v1.y = acc[i][5] + bia1.y;
        v1.z = acc[i][6] + bia1.z; v1.w = acc[i][7] + bia1.w;
        *(float4*)(outp)     = v0;
        *(float4*)(outp + 4) = v1;
    }
}

// ---------------------------------------------------------------------------
// Persistent recurrence: 128 blocks = dir(2) x jtile(64), 256 threads.
// Block caches its 8-j weight slice (3 gates x 8 x 512 = 48KB) in smem once.
// Each step: stage h_prev (32b x 512) into smem, per-warp j-column GEMV with
// lane = (bg in 2) x (kc in 16) K-split, xor-shuffle reduce, all 32 lanes
// finish one batch each, write y. Per-direction release/acquire barrier.
// hs stride 515 (odd) -> bank(b*515+k) patterns conflict-free.
// ---------------------------------------------------------------------------
__global__ void __launch_bounds__(256, 1) gru_persist(
    const float* __restrict__ wh_f, const float* __restrict__ bh_f,
    const float* __restrict__ wh_b, const float* __restrict__ bh_b,
    float* __restrict__ y)
{
    extern __shared__ float sm[];
    float* ws = sm;               // [3][8][512] = 12288 floats
    float* hs = sm + 3 * 8 * HID; // [32][515]   = 16480 floats

    const int blk = blockIdx.x;   // 0..127
    const int dir = blk >> 6;
    const int jt  = blk & 63;
    const float* wh = dir ? wh_b : wh_f;
    const float* bh = dir ? bh_b : bh_f;

    const int tid  = threadIdx.x;
    const int w    = tid >> 5;
    const int lane = tid & 31;
    const int bg   = lane >> 4;   // 0..1
    const int kc   = lane & 15;   // 0..15
    const int j    = jt * 8 + w;

    // preload weight slice: ws[g*4096 + jw*512 + k] = wh[(g*HID + jt*8+jw)*HID + k]
    for (int i = tid; i < 3 * 8 * HID; i += 256) {
        int g  = i >> 12;
        int r  = i & 4095;
        int jw = r >> 9;
        int k  = r & 511;
        ws[i] = wh[((size_t)g * HID + jt * 8 + jw) * HID + k];
    }

    __shared__ unsigned s_base;
    if (tid == 0) s_base = g_gen[dir];
    __syncthreads();
    const unsigned base = s_base;

    const float* wr = ws + w * HID;
    const float* wz = wr + 4096;
    const float* wn = wr + 8192;

    const float bRv = __ldg(bh + j);
    const float bZv = __ldg(bh + HID + j);
    const float bNv = __ldg(bh + 2 * HID + j);

    for (int t = 0; t < SEQ; ++t) {
        const int tt    = dir ? (SEQ - 1 - t) : t;
        const int tprev = dir ? (tt + 1) : (tt - 1);

        // stage h_prev
        if (t == 0) {
            for (int i = tid; i < BATCH * HID; i += 256)
                hs[(i >> 9) * 515 + (i & 511)] = 0.f;
        } else {
            for (int i = tid; i < BATCH * HID; i += 256) {
                int b = i >> 9, k = i & 511;
                hs[b * 515 + k] =
                    y[((size_t)b * SEQ + tprev) * (2 * HID) + dir * HID + k];
            }
        }
        __syncthreads();

        float aR[16], aZ[16], aN[16];
#pragma unroll
        for (int i = 0; i < 16; i++) { aR[i] = 0.f; aZ[i] = 0.f; aN[i] = 0.f; }

#pragma unroll 4
        for (int kk = 0; kk < 32; ++kk) {
            int k = kk * 16 + kc;
            float vr = wr[k], vz = wz[k], vn = wn[k];
#pragma unroll
            for (int bi = 0; bi < 16; ++bi) {
                float h = hs[(bg * 16 + bi) * 515 + k];
                aR[bi] = fmaf(h, vr, aR[bi]);
                aZ[bi] = fmaf(h, vz, aZ[bi]);
                aN[bi] = fmaf(h, vn, aN[bi]);
            }
        }

        // reduce over the 16 kc lanes (bg groups stay separate: xor < 16)
#pragma unroll
        for (int m = 1; m < 16; m <<= 1) {
#pragma unroll
            for (int bi = 0; bi < 16; ++bi) {
                aR[bi] += __shfl_xor_sync(0xffffffffu, aR[bi], m);
                aZ[bi] += __shfl_xor_sync(0xffffffffu, aZ[bi], m);
                aN[bi] += __shfl_xor_sync(0xffffffffu, aN[bi], m);
            }
        }

        // every lane now holds all 16 reduced sums of its bg-group;
        // pick bi == kc so each of the 32 lanes finishes one batch.
        float sR = 0.f, sZ = 0.f, sN = 0.f;
#pragma unroll
        for (int bi = 0; bi < 16; ++bi)
            if (kc == bi) { sR = aR[bi]; sZ = aZ[bi]; sN = aN[bi]; }
        const int b = bg * 16 + kc;

        const float* gxp = g_gx + ((size_t)(dir * SEQ + tt) * BATCH + b) * G3H + j;
        float R = 1.f / (1.f + __expf(-(gxp[0]       + sR + bRv)));
        float Z = 1.f / (1.f + __expf(-(gxp[HID]     + sZ + bZv)));
        float N = tanhf(gxp[2 * HID] + R * (sN + bNv));
        float hp = hs[b * 515 + j];
        y[((size_t)b * SEQ + tt) * (2 * HID) + dir * HID + j] =
            (1.f - Z) * N + Z * hp;

        // per-direction grid barrier (skip after final step; kernel end syncs)
        if (t != SEQ - 1) {
            __syncthreads();
            if (tid == 0) {
                __threadfence();
                unsigned old = atom_add_release(&g_arrive[dir], 1u);
                if (old == 63u) {
                    g_arrive[dir] = 0u;                 // ordered by release below
                    atom_add_release(&g_gen[dir], 1u);
                } else {
                    unsigned target = base + (unsigned)t + 1u;
                    while (ld_acquire(&g_gen[dir]) < target) {}
                }
            }
            __syncthreads();
        }
    }
}

// ---------------------------------------------------------------------------
// Final hidden states: h_fw[l][b][h] = y_l[b][S-1][h]; h_bw = y_l[b][0][H+h]
// ---------------------------------------------------------------------------
__global__ void final_h(const float* __restrict__ y0,
                        const float* __restrict__ y1,
                        float* __restrict__ hf, float* __restrict__ hb)
{
    int i = blockIdx.x * blockDim.x + threadIdx.x;
    if (i >= 2 * BATCH * HID) return;
    int l = i >> 14;
    int b = (i >> 9) & 31;
    int h = i & 511;
    const float* yy = l ? y1 : y0;
    hf[i] = yy[((size_t)b * SEQ + (SEQ - 1)) * (2 * HID) + h];
    hb[i] = yy[((size_t)b * SEQ + 0) * (2 * HID) + HID + h];
}

// ---------------------------------------------------------------------------
extern "C" void kernel_launch(void* const* d_in, const int* in_sizes, int n_in,
                              void* d_out, int out_size)
{
    const float* x     = (const float*)d_in[0];
    const float* wx_f0 = (const float*)d_in[1];
    const float* bx_f0 = (const float*)d_in[2];
    const float* wh_f0 = (const float*)d_in[3];
    const float* bh_f0 = (const float*)d_in[4];
    const float* wx_b0 = (const float*)d_in[5];
    const float* bx_b0 = (const float*)d_in[6];
    const float* wh_b0 = (const float*)d_in[7];
    const float* bh_b0 = (const float*)d_in[8];
    const float* wx_f1 = (const float*)d_in[9];
    const float* bx_f1 = (const float*)d_in[10];
    const float* wh_f1 = (const float*)d_in[11];
    const float* bh_f1 = (const float*)d_in[12];
    const float* wx_b1 = (const float*)d_in[13];
    const float* bx_b1 = (const float*)d_in[14];
    const float* wh_b1 = (const float*)d_in[15];
    const float* bh_b1 = (const float*)d_in[16];

    float* out = (float*)d_out;
    float* y1  = out;                                     // [32][512][1024]
    float* hf  = out + (size_t)BATCH * SEQ * 2 * HID;     // [2][32][512]
    float* hb  = hf + (size_t)2 * BATCH * HID;

    float* y0 = nullptr;
    cudaGetSymbolAddress((void**)&y0, g_y0);

    static int smem_set = 0;
    const int SMEM = (3 * 8 * HID + 32 * 515) * 4;        // 115072 B
    if (!smem_set) {
        cudaFuncSetAttribute(gru_persist,
                             cudaFuncAttributeMaxDynamicSharedMemorySize, SMEM);
        smem_set = 1;
    }

    dim3 gg(MROWS / BM, G3H / BN, 2);

    // layer 0
    gemm_gx<<<gg, 256>>>(x, 512, wx_f0, bx_f0, wx_b0, bx_b0);
    gru_persist<<<128, 256, SMEM>>>(wh_f0, bh_f0, wh_b0, bh_b0, y0);

    // layer 1 (input = y0, in_dim = 1024)
    gemm_gx<<<gg, 256>>>(y0, 1024, wx_f1, bx_f1, wx_b1, bx_b1);
    gru_persist<<<128, 256, SMEM>>>(wh_f1, bh_f1, wh_b1, bh_b1, y1);

    final_h<<<(2 * BATCH * HID + 255) / 256, 256>>>(y0, y1, hf, hb);
}

// round 3
// speedup vs baseline: 1.5745x; 1.5745x over previous
#include <cuda_runtime.h>
#include <cuda_bf16.h>
#include <cstddef>

// ---------------------------------------------------------------------------
// BiGRU: B=32, S=512, I=512, H=512, L=2, bidirectional.
//   gx  = x @ wx^T + bx  (tf32 tensor-core GEMM, [dir][s][b][3H])
//   per step: gh = h @ wh^T + bh  (fp32 persistent kernel, grid barrier)
// ---------------------------------------------------------------------------

#define BATCH 32
#define SEQ   512
#define HID   512
#define G3H   1536
#define MROWS (SEQ * BATCH)   // 16384

__device__ float g_gx[(size_t)2 * MROWS * G3H];          // gate preactivations
__device__ float g_y0[(size_t)BATCH * SEQ * 2 * HID];    // layer-0 output
__device__ float g_h[(size_t)2 * HID * BATCH];           // dense h state [dir][j][b]
__device__ unsigned g_arrive[2];
__device__ unsigned g_gen[2];

__device__ __forceinline__ unsigned atom_add_release(unsigned* p, unsigned v) {
    unsigned old;
    asm volatile("atom.add.release.gpu.u32 %0, [%1], %2;"
                 : "=r"(old) : "l"(p), "r"(v) : "memory");
    return old;
}
__device__ __forceinline__ unsigned ld_acquire(unsigned* p) {
    unsigned v;
    asm volatile("ld.acquire.gpu.u32 %0, [%1];" : "=r"(v) : "l"(p) : "memory");
    return v;
}
__device__ __forceinline__ unsigned f2tf32(float x) {
    unsigned u;
    asm("cvt.rna.tf32.f32 %0, %1;" : "=r"(u) : "f"(x));
    return u;
}

// ---------------------------------------------------------------------------
// tf32 GEMM: gx[dir][s*32+b][n] = sum_k X[b][s][k] * W[n][k] + bias[n]
// 128x128 block tile, BK=16, 8 warps as 2(M)x4(N), warp tile 64x32,
// mma.m16n8k8: 4 m-tiles x 4 n-tiles. Smem rows padded to 20 floats
// (conflict-free fragment LDS).
// ---------------------------------------------------------------------------
#define GPAD 20

__global__ void __launch_bounds__(256) gemm_gx(
    const float* __restrict__ X, int in_dim,
    const float* __restrict__ Wf, const float* __restrict__ bf,
    const float* __restrict__ Wb, const float* __restrict__ bb)
{
    __shared__ float As[128 * GPAD];
    __shared__ float Ws[128 * GPAD];

    const int dir = blockIdx.z;
    const float* W    = dir ? Wb : Wf;
    const float* bias = dir ? bb : bf;
    const int m0 = blockIdx.x * 128;
    const int n0 = blockIdx.y * 128;
    const int tid  = threadIdx.x;
    const int warp = tid >> 5;
    const int lane = tid & 31;
    const int wm = warp >> 2;          // 0..1  (64 M-rows)
    const int wn = warp & 3;           // 0..3  (32 N-cols)
    const int gid = lane >> 2;         // 0..7
    const int tg  = lane & 3;          // 0..3

    float acc[16][4];
#pragma unroll
    for (int i = 0; i < 16; i++)
#pragma unroll
        for (int c = 0; c < 4; c++) acc[i][c] = 0.f;

    const unsigned* Asu = (const unsigned*)As;
    const unsigned* Wsu = (const unsigned*)Ws;

    for (int k0 = 0; k0 < in_dim; k0 += 16) {
#pragma unroll
        for (int ld = 0; ld < 2; ld++) {
            int idx = tid + ld * 256;            // 0..511
            int row = idx >> 2;                  // 0..127
            int kq  = (idx & 3) << 2;            // 0,4,8,12
            int m = m0 + row;
            float4 av = *(const float4*)(X +
                ((size_t)(m & 31) * SEQ + (size_t)(m >> 5)) * in_dim + k0 + kq);
            unsigned* ap = (unsigned*)&As[row * GPAD + kq];
            ap[0] = f2tf32(av.x); ap[1] = f2tf32(av.y);
            ap[2] = f2tf32(av.z); ap[3] = f2tf32(av.w);
            float4 wv = *(const float4*)(W +
                (size_t)(n0 + row) * in_dim + k0 + kq);
            unsigned* wp = (unsigned*)&Ws[row * GPAD + kq];
            wp[0] = f2tf32(wv.x); wp[1] = f2tf32(wv.y);
            wp[2] = f2tf32(wv.z); wp[3] = f2tf32(wv.w);
        }
        __syncthreads();

#pragma unroll
        for (int kk = 0; kk < 16; kk += 8) {
            unsigned a[4][4], b[4][2];
#pragma unroll
            for (int mt = 0; mt < 4; mt++) {
                int r = wm * 64 + mt * 16 + gid;
                a[mt][0] = Asu[(r)     * GPAD + kk + tg];
                a[mt][1] = Asu[(r + 8) * GPAD + kk + tg];
                a[mt][2] = Asu[(r)     * GPAD + kk + tg + 4];
                a[mt][3] = Asu[(r + 8) * GPAD + kk + tg + 4];
            }
#pragma unroll
            for (int nt = 0; nt < 4; nt++) {
                int c = wn * 32 + nt * 8 + gid;
                b[nt][0] = Wsu[c * GPAD + kk + tg];
                b[nt][1] = Wsu[c * GPAD + kk + tg + 4];
            }
#pragma unroll
            for (int mt = 0; mt < 4; mt++)
#pragma unroll
                for (int nt = 0; nt < 4; nt++) {
                    float* d = acc[mt * 4 + nt];
                    asm volatile(
                        "mma.sync.aligned.m16n8k8.row.col.f32.tf32.tf32.f32 "
                        "{%0,%1,%2,%3}, {%4,%5,%6,%7}, {%8,%9}, {%0,%1,%2,%3};"
                        : "+f"(d[0]), "+f"(d[1]), "+f"(d[2]), "+f"(d[3])
                        : "r"(a[mt][0]), "r"(a[mt][1]), "r"(a[mt][2]), "r"(a[mt][3]),
                          "r"(b[nt][0]), "r"(b[nt][1]));
                }
        }
        __syncthreads();
    }

    // epilogue: add bias, write float2 pairs
#pragma unroll
    for (int mt = 0; mt < 4; mt++) {
#pragma unroll
        for (int nt = 0; nt < 4; nt++) {
            int c = n0 + wn * 32 + nt * 8 + 2 * tg;
            float b0 = bias[c], b1 = bias[c + 1];
            int r0 = m0 + wm * 64 + mt * 16 + gid;
            float* d = acc[mt * 4 + nt];
            float2 v0 = {d[0] + b0, d[1] + b1};
            float2 v1 = {d[2] + b0, d[3] + b1};
            *(float2*)(g_gx + ((size_t)dir * MROWS + r0) * G3H + c) = v0;
            *(float2*)(g_gx + ((size_t)dir * MROWS + r0 + 8) * G3H + c) = v1;
        }
    }
}

// ---------------------------------------------------------------------------
// Persistent recurrence: 128 blocks = dir(2) x jtile(64), 512 threads.
// Warp w -> (j_local = w>>1, khalf = w&1); lane = batch. No shuffles.
// smem: ws[3][8][512] weights, hs[512][36] h state (k-major), red exchange.
// ---------------------------------------------------------------------------
__global__ void __launch_bounds__(512, 1) gru_persist(
    const float* __restrict__ wh_f, const float* __restrict__ bh_f,
    const float* __restrict__ wh_b, const float* __restrict__ bh_b,
    float* __restrict__ y)
{
    extern __shared__ float sm[];
    float* ws  = sm;                    // 12288 floats
    float* hs  = sm + 12288;            // 512*36 = 18432 floats
    float* red = hs + 18432;            // 8*3*32 = 768 floats

    const int blk = blockIdx.x;         // 0..127
    const int dir = blk >> 6;
    const int jt  = blk & 63;
    const float* wh = dir ? wh_b : wh_f;
    const float* bh = dir ? bh_b : bh_f;

    const int tid  = threadIdx.x;
    const int w    = tid >> 5;
    const int lane = tid & 31;          // = batch b
    const int jl   = w >> 1;            // 0..7
    const int kh   = w & 1;             // K half
    const int j    = jt * 8 + jl;

    for (int i = tid; i < 3 * 8 * HID; i += 512) {
        int g = i >> 12, r = i & 4095, jw = r >> 9, k = r & 511;
        ws[i] = wh[((size_t)g * HID + jt * 8 + jw) * HID + k];
    }

    __shared__ unsigned s_base;
    if (tid == 0) s_base = g_gen[dir];
    __syncthreads();
    const unsigned base = s_base;

    const float bR = __ldg(bh + j);
    const float bZ = __ldg(bh + HID + j);
    const float bN = __ldg(bh + 2 * HID + j);

    const float* wrp = ws + jl * HID;
    const float* wzp = wrp + 4096;
    const float* wnp = wrp + 8192;

    for (int t = 0; t < SEQ; ++t) {
        const int tt = dir ? (SEQ - 1 - t) : t;

        // stage h_prev into hs[k][b] (pad 36)
        if (t == 0) {
            for (int i = tid; i < 512 * 36; i += 512) hs[i] = 0.f;
        } else {
            const float* hsrc = g_h + (size_t)dir * HID * BATCH;
#pragma unroll
            for (int it = 0; it < 8; ++it) {
                int idx = tid + it * 512;
                int k = idx >> 3, bq = (idx & 7) << 2;
                float4 v = *(const float4*)(hsrc + k * BATCH + bq);
                *(float4*)&hs[k * 36 + bq] = v;
            }
        }
        __syncthreads();

        // prefetch gx (kh==0 lanes do the epilogue)
        float gr = 0.f, gz = 0.f, gn = 0.f;
        if (kh == 0) {
            const float* gxp = g_gx +
                ((size_t)(dir * SEQ + tt) * BATCH + lane) * G3H + j;
            gr = __ldg(gxp); gz = __ldg(gxp + HID); gn = __ldg(gxp + 2 * HID);
        }

        float sR = 0.f, sZ = 0.f, sN = 0.f;
        const int k0 = kh * 256;
#pragma unroll 8
        for (int k = k0; k < k0 + 256; k += 4) {
            float4 wr4 = *(const float4*)&wrp[k];
            float4 wz4 = *(const float4*)&wzp[k];
            float4 wn4 = *(const float4*)&wnp[k];
            float h0 = hs[(k + 0) * 36 + lane];
            float h1 = hs[(k + 1) * 36 + lane];
            float h2 = hs[(k + 2) * 36 + lane];
            float h3 = hs[(k + 3) * 36 + lane];
            sR = fmaf(h0, wr4.x, sR); sZ = fmaf(h0, wz4.x, sZ); sN = fmaf(h0, wn4.x, sN);
            sR = fmaf(h1, wr4.y, sR); sZ = fmaf(h1, wz4.y, sZ); sN = fmaf(h1, wn4.y, sN);
            sR = fmaf(h2, wr4.z, sR); sZ = fmaf(h2, wz4.z, sZ); sN = fmaf(h2, wn4.z, sN);
            sR = fmaf(h3, wr4.w, sR); sZ = fmaf(h3, wz4.w, sZ); sN = fmaf(h3, wn4.w, sN);
        }

        if (kh == 1) {
            red[jl * 96 + lane]      = sR;
            red[jl * 96 + 32 + lane] = sZ;
            red[jl * 96 + 64 + lane] = sN;
        }
        __syncthreads();

        if (kh == 0) {
            sR += red[jl * 96 + lane];
            sZ += red[jl * 96 + 32 + lane];
            sN += red[jl * 96 + 64 + lane];
            float R = 1.f / (1.f + __expf(-(gr + sR + bR)));
            float Z = 1.f / (1.f + __expf(-(gz + sZ + bZ)));
            float N = tanhf(gn + R * (sN + bN));
            float hp = hs[j * 36 + lane];
            float hn = (1.f - Z) * N + Z * hp;
            y[((size_t)lane * SEQ + tt) * (2 * HID) + dir * HID + j] = hn;
            g_h[((size_t)dir * HID + j) * BATCH + lane] = hn;
        }

        if (t != SEQ - 1) {
            __syncthreads();
            if (tid == 0) {
                __threadfence();
                unsigned old = atom_add_release(&g_arrive[dir], 1u);
                if (old == 63u) {
                    g_arrive[dir] = 0u;
                    atom_add_release(&g_gen[dir], 1u);
                } else {
                    unsigned target = base + (unsigned)t + 1u;
                    while (ld_acquire(&g_gen[dir]) < target) {}
                }
            }
            __syncthreads();
        }
    }
}

// ---------------------------------------------------------------------------
__global__ void final_h(const float* __restrict__ y0,
                        const float* __restrict__ y1,
                        float* __restrict__ hf, float* __restrict__ hb)
{
    int i = blockIdx.x * blockDim.x + threadIdx.x;
    if (i >= 2 * BATCH * HID) return;
    int l = i >> 14;
    int b = (i >> 9) & 31;
    int h = i & 511;
    const float* yy = l ? y1 : y0;
    hf[i] = yy[((size_t)b * SEQ + (SEQ - 1)) * (2 * HID) + h];
    hb[i] = yy[((size_t)b * SEQ + 0) * (2 * HID) + HID + h];
}

// ---------------------------------------------------------------------------
extern "C" void kernel_launch(void* const* d_in, const int* in_sizes, int n_in,
                              void* d_out, int out_size)
{
    const float* x     = (const float*)d_in[0];
    const float* wx_f0 = (const float*)d_in[1];
    const float* bx_f0 = (const float*)d_in[2];
    const float* wh_f0 = (const float*)d_in[3];
    const float* bh_f0 = (const float*)d_in[4];
    const float* wx_b0 = (const float*)d_in[5];
    const float* bx_b0 = (const float*)d_in[6];
    const float* wh_b0 = (const float*)d_in[7];
    const float* bh_b0 = (const float*)d_in[8];
    const float* wx_f1 = (const float*)d_in[9];
    const float* bx_f1 = (const float*)d_in[10];
    const float* wh_f1 = (const float*)d_in[11];
    const float* bh_f1 = (const float*)d_in[12];
    const float* wx_b1 = (const float*)d_in[13];
    const float* bx_b1 = (const float*)d_in[14];
    const float* wh_b1 = (const float*)d_in[15];
    const float* bh_b1 = (const float*)d_in[16];

    float* out = (float*)d_out;
    float* y1  = out;
    float* hf  = out + (size_t)BATCH * SEQ * 2 * HID;
    float* hb  = hf + (size_t)2 * BATCH * HID;

    float* y0 = nullptr;
    cudaGetSymbolAddress((void**)&y0, g_y0);

    static int smem_set = 0;
    const int SMEM = (12288 + 512 * 36 + 768) * 4;   // 125952 B
    if (!smem_set) {
        cudaFuncSetAttribute(gru_persist,
                             cudaFuncAttributeMaxDynamicSharedMemorySize, SMEM);
        smem_set = 1;
    }

    dim3 gg(MROWS / 128, G3H / 128, 2);

    gemm_gx<<<gg, 256>>>(x, 512, wx_f0, bx_f0, wx_b0, bx_b0);
    gru_persist<<<128, 512, SMEM>>>(wh_f0, bh_f0, wh_b0, bh_b0, y0);

    gemm_gx<<<gg, 256>>>(y0, 1024, wx_f1, bx_f1, wx_b1, bx_b1);
    gru_persist<<<128, 512, SMEM>>>(wh_f1, bh_f1, wh_b1, bh_b1, y1);

    final_h<<<(2 * BATCH * HID + 255) / 256, 256>>>(y0, y1, hf, hb);
}